// round 4
// baseline (speedup 1.0000x reference)
#include <cuda_runtime.h>
#include <cuda_bf16.h>
#include <math.h>
#include <stdint.h>

#define L_LAYERS 4
#define T_SEQ    4096
#define DM       2048
#define DH       1024
#define KQ       4096        // int8 correction K = 2*DM
#define BN_EPS   1e-5f

// scan chunking
#define SCH  16
#define SCHL (T_SEQ / SCH)   // 256

// ---------------------------------------------------------------------------
// Scratch (no cudaMalloc allowed)
// ---------------------------------------------------------------------------
__device__ float g_x [T_SEQ * DM];
__device__ float g_xn[T_SEQ * DM];
__device__ float g_t1[T_SEQ * DM];
__device__ float g_u [T_SEQ * DM];
__device__ float g_v [T_SEQ * DM];
__device__ float g_corr[T_SEQ * DM];
__device__ __nv_bfloat16 g_ah[(size_t)T_SEQ * DM];   // act hi (bf16)
__device__ int8_t        g_aq[(size_t)T_SEQ * KQ];   // act int8 [q(a) | q(al)]
__device__ __nv_bfloat16 g_wh[(size_t)DM * DM];      // weight hi (bf16)
__device__ int8_t        g_wq[(size_t)DM * KQ];      // weight int8 [q(wl) | q(wh)]
__device__ float g_mean[DM], g_var[DM];
__device__ float g_bnp[8][2][DM];
__device__ float g_carr[SCH * DH], g_cari[SCH * DH];
__device__ float g_cinr[SCH * DH], g_cini[SCH * DH];

// ---------------------------------------------------------------------------
// PTX helpers
// ---------------------------------------------------------------------------
__device__ __forceinline__ void cp16(uint32_t saddr, const void* g) {
    asm volatile("cp.async.cg.shared.global [%0], [%1], 16;\n" :: "r"(saddr), "l"(g));
}
__device__ __forceinline__ void cp_commit() {
    asm volatile("cp.async.commit_group;\n");
}
template<int N> __device__ __forceinline__ void cp_wait() {
    asm volatile("cp.async.wait_group %0;\n" :: "n"(N));
}
__device__ __forceinline__ void ldsm_x4(uint32_t* r, uint32_t addr) {
    asm volatile("ldmatrix.sync.aligned.m8n8.x4.shared.b16 {%0,%1,%2,%3}, [%4];\n"
                 : "=r"(r[0]), "=r"(r[1]), "=r"(r[2]), "=r"(r[3]) : "r"(addr));
}
__device__ __forceinline__ void mma_bf16(float* c, const uint32_t* a, uint32_t b0, uint32_t b1) {
    asm volatile("mma.sync.aligned.m16n8k16.row.col.f32.bf16.bf16.f32 "
                 "{%0,%1,%2,%3}, {%4,%5,%6,%7}, {%8,%9}, {%0,%1,%2,%3};\n"
                 : "+f"(c[0]), "+f"(c[1]), "+f"(c[2]), "+f"(c[3])
                 : "r"(a[0]), "r"(a[1]), "r"(a[2]), "r"(a[3]), "r"(b0), "r"(b1));
}
__device__ __forceinline__ void mma_s8(int* c, const uint32_t* a, uint32_t b0, uint32_t b1) {
    asm volatile("mma.sync.aligned.m16n8k32.row.col.s32.s8.s8.s32 "
                 "{%0,%1,%2,%3}, {%4,%5,%6,%7}, {%8,%9}, {%0,%1,%2,%3};\n"
                 : "+r"(c[0]), "+r"(c[1]), "+r"(c[2]), "+r"(c[3])
                 : "r"(a[0]), "r"(a[1]), "r"(a[2]), "r"(a[3]), "r"(b0), "r"(b1));
}

// ---------------------------------------------------------------------------
// bf16 main GEMM (NT): C[m][n] = sum_{k<2048} A[m][k]*B[n][k] + corr + bias
// BM=BN=128, BK=32, 256 thr, 4 stages.
// ---------------------------------------------------------------------------
#define STAGES 4
#define BK 32
#define PADK 40
#define STAGE_BYTES (2 * 128 * PADK * 2)
#define KITERS (DM / BK)                    // 64

__global__ __launch_bounds__(256) void gemm_bf16(
    const __nv_bfloat16* __restrict__ A, const __nv_bfloat16* __restrict__ B,
    const float* __restrict__ bias, const float* __restrict__ corr,
    float* __restrict__ C)
{
    extern __shared__ __nv_bfloat16 sh[];
    const int bm = blockIdx.y * 128, bn = blockIdx.x * 128;
    const int tid = threadIdx.x, lane = tid & 31, warp = tid >> 5;
    const int wm = (warp >> 2) * 64, wn = (warp & 3) * 32;

    uint32_t sbase = (uint32_t)__cvta_generic_to_shared(sh);

    const int r0 = tid >> 2, seg = (tid & 3) * 8;
    uint32_t dA0 = sbase + (r0 * PADK + seg) * 2;
    uint32_t dA1 = sbase + ((r0 + 64) * PADK + seg) * 2;
    uint32_t dB0 = sbase + (128 * PADK + r0 * PADK + seg) * 2;
    uint32_t dB1 = dB0 + 64 * PADK * 2;
    const __nv_bfloat16* gA0 = A + (size_t)(bm + r0) * DM + seg;
    const __nv_bfloat16* gA1 = A + (size_t)(bm + r0 + 64) * DM + seg;
    const __nv_bfloat16* gB0 = B + (size_t)(bn + r0) * DM + seg;
    const __nv_bfloat16* gB1 = B + (size_t)(bn + r0 + 64) * DM + seg;

    uint32_t aoff[4], boff[2];
    #pragma unroll
    for (int mi = 0; mi < 4; mi++)
        aoff[mi] = ((wm + mi * 16 + (lane & 15)) * PADK + (lane >> 4) * 8) * 2;
    #pragma unroll
    for (int nh = 0; nh < 2; nh++)
        boff[nh] = (128 * PADK + (wn + nh * 16 + (lane >> 4) * 8 + (lane & 7)) * PADK
                    + ((lane >> 3) & 1) * 8) * 2;

    float acc[4][4][4] = {};

    auto load_stage = [&](int s) {
        uint32_t so = (uint32_t)(s & (STAGES - 1)) * STAGE_BYTES;
        int k0 = s * BK;
        cp16(dA0 + so, gA0 + k0);
        cp16(dA1 + so, gA1 + k0);
        cp16(dB0 + so, gB0 + k0);
        cp16(dB1 + so, gB1 + k0);
    };

    load_stage(0); cp_commit();
    load_stage(1); cp_commit();
    load_stage(2); cp_commit();

    for (int it = 0; it < KITERS; it++) {
        cp_wait<2>();
        __syncthreads();
        uint32_t sb = sbase + (uint32_t)(it & (STAGES - 1)) * STAGE_BYTES;

        #pragma unroll
        for (int ks = 0; ks < 2; ks++) {
            uint32_t ko = sb + ks * 32;
            uint32_t a[4][4], b[2][4];
            #pragma unroll
            for (int mi = 0; mi < 4; mi++) ldsm_x4(a[mi], ko + aoff[mi]);
            #pragma unroll
            for (int nh = 0; nh < 2; nh++) ldsm_x4(b[nh], ko + boff[nh]);
            #pragma unroll
            for (int mi = 0; mi < 4; mi++)
                #pragma unroll
                for (int ni = 0; ni < 4; ni++)
                    mma_bf16(acc[mi][ni], a[mi], b[ni >> 1][(ni & 1) * 2],
                             b[ni >> 1][(ni & 1) * 2 + 1]);
        }

        if (it + 3 < KITERS) load_stage(it + 3);
        cp_commit();
    }

    const int er = lane >> 2, ec = (lane & 3) * 2;
    #pragma unroll
    for (int mi = 0; mi < 4; mi++) {
        int row = bm + wm + mi * 16 + er;
        #pragma unroll
        for (int ni = 0; ni < 4; ni++) {
            int col = bn + wn + ni * 8 + ec;
            float b0 = 0.f, b1 = 0.f;
            if (bias) { b0 = bias[col]; b1 = bias[col + 1]; }
            float2 c0 = *(const float2*)&corr[(size_t)row * DM + col];
            float2 c1 = *(const float2*)&corr[(size_t)(row + 8) * DM + col];
            float2 v;
            v.x = acc[mi][ni][0] + b0 + c0.x; v.y = acc[mi][ni][1] + b1 + c0.y;
            *(float2*)&C[(size_t)row * DM + col] = v;
            v.x = acc[mi][ni][2] + b0 + c1.x; v.y = acc[mi][ni][3] + b1 + c1.y;
            *(float2*)&C[(size_t)(row + 8) * DM + col] = v;
        }
    }
}

// ---------------------------------------------------------------------------
// int8 correction GEMM (NT): corr[m][n] = scale * sum_{k<4096} A[m][k]*B[n][k]
// BM=BN=128, BKB=64 int8, 256 thr, 4 stages. Plain LDS fragment loads.
// ---------------------------------------------------------------------------
#define QPAD 80
#define QSTG (2 * 128 * QPAD)     // 20480 B per stage
#define QITERS (KQ / 64)          // 64

__global__ __launch_bounds__(256) void gemm_s8(
    const int8_t* __restrict__ A, const int8_t* __restrict__ B,
    float scale, float* __restrict__ C)
{
    extern __shared__ char shq[];
    const int bm = blockIdx.y * 128, bn = blockIdx.x * 128;
    const int tid = threadIdx.x, lane = tid & 31, warp = tid >> 5;
    const int wm = (warp >> 2) * 64, wn = (warp & 3) * 32;

    uint32_t sbase = (uint32_t)__cvta_generic_to_shared(shq);

    const int r0 = tid >> 2, seg = (tid & 3) * 16;
    uint32_t dA0 = sbase + r0 * QPAD + seg;
    uint32_t dA1 = sbase + (r0 + 64) * QPAD + seg;
    uint32_t dB0 = sbase + 128 * QPAD + r0 * QPAD + seg;
    uint32_t dB1 = dB0 + 64 * QPAD;
    const int8_t* gA0 = A + (size_t)(bm + r0) * KQ + seg;
    const int8_t* gA1 = A + (size_t)(bm + r0 + 64) * KQ + seg;
    const int8_t* gB0 = B + (size_t)(bn + r0) * KQ + seg;
    const int8_t* gB1 = B + (size_t)(bn + r0 + 64) * KQ + seg;

    int acc[4][4][4] = {};

    auto load_stage = [&](int s) {
        uint32_t so = (uint32_t)(s & 3) * QSTG;
        int k0 = s * 64;
        cp16(dA0 + so, gA0 + k0);
        cp16(dA1 + so, gA1 + k0);
        cp16(dB0 + so, gB0 + k0);
        cp16(dB1 + so, gB1 + k0);
    };

    load_stage(0); cp_commit();
    load_stage(1); cp_commit();
    load_stage(2); cp_commit();

    const char* shp = shq;
    const int arow = lane >> 2, akb = (lane & 3) * 4;

    for (int it = 0; it < QITERS; it++) {
        cp_wait<2>();
        __syncthreads();
        uint32_t stg = (uint32_t)(it & 3) * QSTG;

        #pragma unroll
        for (int ks = 0; ks < 2; ks++) {
            int kb = ks * 32 + akb;
            uint32_t a[4][4], b[4][2];
            #pragma unroll
            for (int mi = 0; mi < 4; mi++) {
                const char* p = shp + stg + (wm + mi * 16 + arow) * QPAD + kb;
                a[mi][0] = *(const uint32_t*)p;
                a[mi][1] = *(const uint32_t*)(p + 8 * QPAD);
                a[mi][2] = *(const uint32_t*)(p + 16);
                a[mi][3] = *(const uint32_t*)(p + 8 * QPAD + 16);
            }
            #pragma unroll
            for (int ni = 0; ni < 4; ni++) {
                const char* p = shp + stg + 128 * QPAD + (wn + ni * 8 + arow) * QPAD + kb;
                b[ni][0] = *(const uint32_t*)p;
                b[ni][1] = *(const uint32_t*)(p + 16);
            }
            #pragma unroll
            for (int mi = 0; mi < 4; mi++)
                #pragma unroll
                for (int ni = 0; ni < 4; ni++)
                    mma_s8(acc[mi][ni], a[mi], b[ni][0], b[ni][1]);
        }

        if (it + 3 < QITERS) load_stage(it + 3);
        cp_commit();
    }

    const int er = lane >> 2, ec = (lane & 3) * 2;
    #pragma unroll
    for (int mi = 0; mi < 4; mi++) {
        int row = bm + wm + mi * 16 + er;
        #pragma unroll
        for (int ni = 0; ni < 4; ni++) {
            int col = bn + wn + ni * 8 + ec;
            float2 v;
            v.x = (float)acc[mi][ni][0] * scale; v.y = (float)acc[mi][ni][1] * scale;
            *(float2*)&C[(size_t)row * DM + col] = v;
            v.x = (float)acc[mi][ni][2] * scale; v.y = (float)acc[mi][ni][3] * scale;
            *(float2*)&C[(size_t)(row + 8) * DM + col] = v;
        }
    }
}

// ---------------------------------------------------------------------------
// quant / split helpers
// ---------------------------------------------------------------------------
__device__ __forceinline__ int8_t q8(float v) {
    v = fminf(fmaxf(v, -127.f), 127.f);
    return (int8_t)__float2int_rn(v);
}
// acts: hi bf16 at [m*DM+n]; int8 q(a) at [m*KQ+n], q(al) at [m*KQ+DM+n]
__device__ __forceinline__ void emit_act(float v, int m, int n,
                                         __nv_bfloat16* ah, int8_t* aq, float invSa) {
    __nv_bfloat16 h = __float2bfloat16(v);
    float al = v - __bfloat162float(h);
    ah[(size_t)m * DM + n] = h;
    aq[(size_t)m * KQ + n]      = q8(v * invSa);
    aq[(size_t)m * KQ + DM + n] = q8(al * invSa * 128.f);
}
// weights: hi bf16 at [n*DM+k]; int8 q(wl) at [n*KQ+k], q(wh) at [n*KQ+DM+k]
__device__ __forceinline__ void emit_wt(float v, int n, int k,
                                        __nv_bfloat16* wh, int8_t* wq, float invSw) {
    __nv_bfloat16 h = __float2bfloat16(v);
    float hf = __bfloat162float(h);
    float wl = v - hf;
    wh[(size_t)n * DM + k] = h;
    wq[(size_t)n * KQ + k]      = q8(wl * invSw * 128.f);
    wq[(size_t)n * KQ + DM + k] = q8(hf * invSw);
}

// ---------------------------------------------------------------------------
// BatchNorm (two-phase stats)
// ---------------------------------------------------------------------------
__global__ void bnp1(const float* __restrict__ x)
{
    const int col = blockIdx.x * 32 + (threadIdx.x & 31);
    const int r0  = threadIdx.x >> 5;
    const int t0  = blockIdx.y * 512;
    float s = 0.f, ss = 0.f;
    for (int t = t0 + r0; t < t0 + 512; t += 8) {
        float v = x[(size_t)t * DM + col];
        s += v; ss += v * v;
    }
    __shared__ float sh_s[8][32], sh_ss[8][32];
    sh_s[r0][threadIdx.x & 31]  = s;
    sh_ss[r0][threadIdx.x & 31] = ss;
    __syncthreads();
    if (r0 == 0) {
        for (int r = 1; r < 8; r++) {
            s  += sh_s[r][threadIdx.x & 31];
            ss += sh_ss[r][threadIdx.x & 31];
        }
        g_bnp[blockIdx.y][0][col] = s;
        g_bnp[blockIdx.y][1][col] = ss;
    }
}

__global__ void bnp2()
{
    int col = blockIdx.x * blockDim.x + threadIdx.x;
    float s = 0.f, ss = 0.f;
    #pragma unroll
    for (int r = 0; r < 8; r++) { s += g_bnp[r][0][col]; ss += g_bnp[r][1][col]; }
    float mu = s / (float)T_SEQ;
    g_mean[col] = mu;
    g_var[col]  = ss / (float)T_SEQ - mu * mu;
}

__global__ void bn_fuse(const float* __restrict__ x, float* __restrict__ xn,
                        __nv_bfloat16* __restrict__ ah, int8_t* __restrict__ aq,
                        const float* __restrict__ w, const float* __restrict__ b,
                        float invSa)
{
    int idx = blockIdx.x * blockDim.x + threadIdx.x;
    int n = idx & (DM - 1);
    int m = idx >> 11;
    float inv = rsqrtf(g_var[n] + BN_EPS);
    float v = (x[idx] - g_mean[n]) * inv * w[n] + b[n];
    xn[idx] = v;
    emit_act(v, m, n, ah, aq, invSa);
}

// ---------------------------------------------------------------------------
// Weight packing
// ---------------------------------------------------------------------------
__global__ void pack_w_plain(const float* __restrict__ W,
                             __nv_bfloat16* __restrict__ wh, int8_t* __restrict__ wq,
                             float invSw)
{
    int idx = blockIdx.x * blockDim.x + threadIdx.x;
    int n = idx >> 11, k = idx & (DM - 1);
    emit_wt(W[idx], n, k, wh, wq, invSw);
}

__global__ void pack_Bn(const float* __restrict__ B_re, const float* __restrict__ B_im,
                        const float* __restrict__ gamma_log,
                        __nv_bfloat16* __restrict__ wh, int8_t* __restrict__ wq,
                        float invSw)
{
    int idx = blockIdx.x * blockDim.x + threadIdx.x;
    int n = idx >> 11, k = idx & (DM - 1);
    int jj = n & (DH - 1);
    float g = expf(gamma_log[jj]);
    float v = ((n < DH) ? B_re[(size_t)jj * DM + k] : B_im[(size_t)jj * DM + k]) * g;
    emit_wt(v, n, k, wh, wq, invSw);
}

__global__ void pack_Cc(const float* __restrict__ C_re, const float* __restrict__ C_im,
                        __nv_bfloat16* __restrict__ wh, int8_t* __restrict__ wq,
                        float invSw)
{
    int idx = blockIdx.x * blockDim.x + threadIdx.x;
    int n = idx >> 11, k = idx & (DM - 1);
    float v = (k < DH) ? C_re[(size_t)n * DH + k] : -C_im[(size_t)n * DH + (k - DH)];
    emit_wt(v, n, k, wh, wq, invSw);
}

__global__ void pack_act_plain(const float* __restrict__ X,
                               __nv_bfloat16* __restrict__ ah, int8_t* __restrict__ aq,
                               float invSa)
{
    int idx = blockIdx.x * blockDim.x + threadIdx.x;
    int n = idx & (DM - 1);
    int m = idx >> 11;
    emit_act(X[idx], m, n, ah, aq, invSa);
}

// ---------------------------------------------------------------------------
// LRU scan — chunk-parallel (3 passes)
// ---------------------------------------------------------------------------
__device__ __forceinline__ void lam_of(int j, const float* nu_log, const float* th_log,
                                       float& lr, float& li)
{
    float mag = expf(-expf(nu_log[j]));
    float ph  = expf(th_log[j]);
    lr = mag * cosf(ph);
    li = mag * sinf(ph);
}

__global__ void scan_p1(const float* __restrict__ Bu,
                        const float* __restrict__ nu_log, const float* __restrict__ th_log)
{
    int idx = blockIdx.x * blockDim.x + threadIdx.x;
    int j = idx & (DH - 1), c = idx >> 10;
    float lr, li; lam_of(j, nu_log, th_log, lr, li);
    float hr = 0.f, hi = 0.f;
    int t0 = c * SCHL;
    for (int t = t0; t < t0 + SCHL; t++) {
        float br = Bu[(size_t)t * DM + j];
        float bi = Bu[(size_t)t * DM + DH + j];
        float nhr = lr * hr - li * hi + br;
        float nhi = lr * hi + li * hr + bi;
        hr = nhr; hi = nhi;
    }
    g_carr[c * DH + j] = hr;
    g_cari[c * DH + j] = hi;
}

__global__ void scan_fix(const float* __restrict__ nu_log, const float* __restrict__ th_log)
{
    int j = blockIdx.x * blockDim.x + threadIdx.x;
    float lr, li; lam_of(j, nu_log, th_log, lr, li);
    float ar = lr, ai = li;
    #pragma unroll
    for (int s = 0; s < 8; s++) {       // lam^256
        float nr = ar * ar - ai * ai;
        float ni = 2.f * ar * ai;
        ar = nr; ai = ni;
    }
    float cr = 0.f, ci = 0.f;
    for (int c = 0; c < SCH; c++) {
        g_cinr[c * DH + j] = cr;
        g_cini[c * DH + j] = ci;
        float nr = ar * cr - ai * ci + g_carr[c * DH + j];
        float ni = ar * ci + ai * cr + g_cari[c * DH + j];
        cr = nr; ci = ni;
    }
}

__global__ void scan_p2(const float* __restrict__ Bu,
                        __nv_bfloat16* __restrict__ ah, int8_t* __restrict__ aq,
                        const float* __restrict__ nu_log, const float* __restrict__ th_log,
                        float invSa)
{
    int idx = blockIdx.x * blockDim.x + threadIdx.x;
    int j = idx & (DH - 1), c = idx >> 10;
    float lr, li; lam_of(j, nu_log, th_log, lr, li);
    float hr = g_cinr[c * DH + j], hi = g_cini[c * DH + j];
    int t0 = c * SCHL;
    for (int t = t0; t < t0 + SCHL; t++) {
        float br = Bu[(size_t)t * DM + j];
        float bi = Bu[(size_t)t * DM + DH + j];
        float nhr = lr * hr - li * hi + br;
        float nhi = lr * hi + li * hr + bi;
        hr = nhr; hi = nhi;
        emit_act(hr, t, j, ah, aq, invSa);
        emit_act(hi, t, DH + j, ah, aq, invSa);
    }
}

// ---------------------------------------------------------------------------
// Epilogues
// ---------------------------------------------------------------------------
__global__ void posty_fuse(const float* __restrict__ y, const float* __restrict__ xn,
                           const float* __restrict__ Dv,
                           __nv_bfloat16* __restrict__ ah, int8_t* __restrict__ aq,
                           float invSa)
{
    int idx = blockIdx.x * blockDim.x + threadIdx.x;
    int n = idx & (DM - 1);
    int m = idx >> 11;
    float v = y[idx] + xn[idx] * Dv[n];
    float g = 0.5f * v * (1.f + erff(v * 0.70710678118654752f));
    emit_act(g, m, n, ah, aq, invSa);
}

__global__ void glu_combine(const float* __restrict__ x, const float* __restrict__ u,
                            const float* __restrict__ v, float* __restrict__ out)
{
    int idx = blockIdx.x * blockDim.x + threadIdx.x;
    float vv = v[idx];
    float s = 1.f / (1.f + expf(-vv));
    out[idx] = x[idx] + u[idx] * s;
}

// ---------------------------------------------------------------------------
// Launch
// ---------------------------------------------------------------------------
extern "C" void kernel_launch(void* const* d_in, const int* in_sizes, int n_in,
                              void* d_out, int out_size)
{
    const float* x_in      = (const float*)d_in[0];
    const float* enc_w     = (const float*)d_in[1];
    const float* enc_b     = (const float*)d_in[2];
    const float* nu_log    = (const float*)d_in[3];
    const float* theta_log = (const float*)d_in[4];
    const float* gamma_log = (const float*)d_in[5];
    const float* B_re      = (const float*)d_in[6];
    const float* B_im      = (const float*)d_in[7];
    const float* C_re      = (const float*)d_in[8];
    const float* C_im      = (const float*)d_in[9];
    const float* Dv        = (const float*)d_in[10];
    const float* norm_w    = (const float*)d_in[11];
    const float* norm_b    = (const float*)d_in[12];
    const float* out1_w    = (const float*)d_in[13];
    const float* out1_b    = (const float*)d_in[14];
    const float* out2_w    = (const float*)d_in[15];
    const float* out2_b    = (const float*)d_in[16];
    float* out = (float*)d_out;
    (void)in_sizes; (void)n_in; (void)out_size;

    float *px, *pxn, *pt1, *pu, *pv, *pcorr;
    __nv_bfloat16 *pah, *pwh;
    int8_t *paq, *pwq;
    cudaGetSymbolAddress((void**)&px,    g_x);
    cudaGetSymbolAddress((void**)&pxn,   g_xn);
    cudaGetSymbolAddress((void**)&pt1,   g_t1);
    cudaGetSymbolAddress((void**)&pu,    g_u);
    cudaGetSymbolAddress((void**)&pv,    g_v);
    cudaGetSymbolAddress((void**)&pcorr, g_corr);
    cudaGetSymbolAddress((void**)&pah,   g_ah);
    cudaGetSymbolAddress((void**)&paq,   g_aq);
    cudaGetSymbolAddress((void**)&pwh,   g_wh);
    cudaGetSymbolAddress((void**)&pwq,   g_wq);

    const int SMEMB = STAGES * STAGE_BYTES;   // 81920
    const int SMEMQ = 4 * QSTG;               // 81920
    cudaFuncSetAttribute(gemm_bf16, cudaFuncAttributeMaxDynamicSharedMemorySize, SMEMB);
    cudaFuncSetAttribute(gemm_s8,   cudaFuncAttributeMaxDynamicSharedMemorySize, SMEMQ);

    dim3 ggrid(DM / 128, T_SEQ / 128);   // (16, 32)
    const int EW = (T_SEQ * DM) / 256;
    const int PW = (DM * DM) / 256;
    dim3 bgrid(DM / 32, 8);

    // fixed quantization scales (power-margined bounds)
    const float Sx = 8.f, Sh = 8.f, Sg = 16.f;        // activations
    const float Sww = 0.0225f, Swb = 0.12f, Swc = 0.22f;  // weights
    auto cs = [](float Sa, float Sw) { return Sa * Sw / (128.f * 16129.f); };

    // Encoder
    pack_act_plain<<<EW, 256>>>(x_in, pah, paq, 127.f / Sx);
    pack_w_plain<<<PW, 256>>>(enc_w, pwh, pwq, 127.f / Sww);
    gemm_s8<<<ggrid, 256, SMEMQ>>>(paq, pwq, cs(Sx, Sww), pcorr);
    gemm_bf16<<<ggrid, 256, SMEMB>>>(pah, pwh, enc_b, pcorr, px);

    for (int l = 0; l < L_LAYERS; l++) {
        const float* nw  = norm_w + l * DM;
        const float* nb  = norm_b + l * DM;
        const float* nu  = nu_log + l * DH;
        const float* th  = theta_log + l * DH;
        const float* gl  = gamma_log + l * DH;
        const float* bre = B_re + (size_t)l * DH * DM;
        const float* bim = B_im + (size_t)l * DH * DM;
        const float* cre = C_re + (size_t)l * DM * DH;
        const float* cim = C_im + (size_t)l * DM * DH;
        const float* dv  = Dv + l * DM;
        const float* w1  = out1_w + (size_t)l * DM * DM;
        const float* b1  = out1_b + l * DM;
        const float* w2  = out2_w + (size_t)l * DM * DM;
        const float* b2  = out2_b + l * DM;

        bnp1<<<bgrid, 256>>>(px);
        bnp2<<<DM / 256, 256>>>();
        bn_fuse<<<EW, 256>>>(px, pxn, pah, paq, nw, nb, 127.f / Sx);

        pack_Bn<<<PW, 256>>>(bre, bim, gl, pwh, pwq, 127.f / Swb);
        gemm_s8<<<ggrid, 256, SMEMQ>>>(paq, pwq, cs(Sx, Swb), pcorr);
        gemm_bf16<<<ggrid, 256, SMEMB>>>(pah, pwh, nullptr, pcorr, pt1);   // Bu

        scan_p1<<<(DH * SCH) / 256, 256>>>(pt1, nu, th);
        scan_fix<<<DH / 256, 256>>>(nu, th);
        scan_p2<<<(DH * SCH) / 256, 256>>>(pt1, pah, paq, nu, th, 127.f / Sh);

        pack_Cc<<<PW, 256>>>(cre, cim, pwh, pwq, 127.f / Swc);
        gemm_s8<<<ggrid, 256, SMEMQ>>>(paq, pwq, cs(Sh, Swc), pcorr);
        gemm_bf16<<<ggrid, 256, SMEMB>>>(pah, pwh, nullptr, pcorr, pt1);   // y raw

        posty_fuse<<<EW, 256>>>(pt1, pxn, dv, pah, paq, 127.f / Sg);

        pack_w_plain<<<PW, 256>>>(w1, pwh, pwq, 127.f / Sww);
        gemm_s8<<<ggrid, 256, SMEMQ>>>(paq, pwq, cs(Sg, Sww), pcorr);
        gemm_bf16<<<ggrid, 256, SMEMB>>>(pah, pwh, b1, pcorr, pu);

        pack_w_plain<<<PW, 256>>>(w2, pwh, pwq, 127.f / Sww);
        gemm_s8<<<ggrid, 256, SMEMQ>>>(paq, pwq, cs(Sg, Sww), pcorr);
        gemm_bf16<<<ggrid, 256, SMEMB>>>(pah, pwh, b2, pcorr, pv);

        float* dst = (l == L_LAYERS - 1) ? out : px;
        glu_combine<<<EW, 256>>>(px, pu, pv, dst);
    }
}

// round 5
// speedup vs baseline: 1.8405x; 1.8405x over previous
#include <cuda_runtime.h>
#include <cuda_bf16.h>
#include <cuda_fp8.h>
#include <math.h>
#include <stdint.h>

#define L_LAYERS 4
#define T_SEQ    4096
#define DM       2048
#define DH       1024
#define KQ       4096        // fp8 correction K = 2*DM bytes
#define KU       2048        // fp8 K in b16 units
#define BN_EPS   1e-5f

// scan chunking
#define SCH  16
#define SCHL (T_SEQ / SCH)   // 256

// ---------------------------------------------------------------------------
// Scratch (no cudaMalloc allowed)
// ---------------------------------------------------------------------------
__device__ float g_x [T_SEQ * DM];
__device__ float g_xn[T_SEQ * DM];
__device__ float g_t1[T_SEQ * DM];
__device__ float g_u [T_SEQ * DM];
__device__ float g_v [T_SEQ * DM];
__device__ float g_corr[T_SEQ * DM];
__device__ __nv_bfloat16 g_ah[(size_t)T_SEQ * DM];   // act hi (bf16)
__device__ uint8_t       g_aq[(size_t)T_SEQ * KQ];   // act fp8 [e4m3(a) | e4m3(al*256)]
__device__ __nv_bfloat16 g_wh[(size_t)DM * DM];      // weight hi (bf16)
__device__ uint8_t       g_wq[(size_t)DM * KQ];      // wt fp8 [e4m3(wl*256) | e4m3(w)]
__device__ float g_mean[DM], g_var[DM];
__device__ float g_bnp[8][2][DM];
__device__ float g_carr[SCH * DH], g_cari[SCH * DH];
__device__ float g_cinr[SCH * DH], g_cini[SCH * DH];

// ---------------------------------------------------------------------------
// PTX helpers
// ---------------------------------------------------------------------------
__device__ __forceinline__ void cp16(uint32_t saddr, const void* g) {
    asm volatile("cp.async.cg.shared.global [%0], [%1], 16;\n" :: "r"(saddr), "l"(g));
}
__device__ __forceinline__ void cp_commit() {
    asm volatile("cp.async.commit_group;\n");
}
template<int N> __device__ __forceinline__ void cp_wait() {
    asm volatile("cp.async.wait_group %0;\n" :: "n"(N));
}
__device__ __forceinline__ void ldsm_x4(uint32_t* r, uint32_t addr) {
    asm volatile("ldmatrix.sync.aligned.m8n8.x4.shared.b16 {%0,%1,%2,%3}, [%4];\n"
                 : "=r"(r[0]), "=r"(r[1]), "=r"(r[2]), "=r"(r[3]) : "r"(addr));
}
__device__ __forceinline__ void mma_bf16(float* c, const uint32_t* a, uint32_t b0, uint32_t b1) {
    asm volatile("mma.sync.aligned.m16n8k16.row.col.f32.bf16.bf16.f32 "
                 "{%0,%1,%2,%3}, {%4,%5,%6,%7}, {%8,%9}, {%0,%1,%2,%3};\n"
                 : "+f"(c[0]), "+f"(c[1]), "+f"(c[2]), "+f"(c[3])
                 : "r"(a[0]), "r"(a[1]), "r"(a[2]), "r"(a[3]), "r"(b0), "r"(b1));
}
__device__ __forceinline__ void mma_e4m3(float* c, const uint32_t* a, uint32_t b0, uint32_t b1) {
    asm volatile("mma.sync.aligned.m16n8k32.row.col.f32.e4m3.e4m3.f32 "
                 "{%0,%1,%2,%3}, {%4,%5,%6,%7}, {%8,%9}, {%0,%1,%2,%3};\n"
                 : "+f"(c[0]), "+f"(c[1]), "+f"(c[2]), "+f"(c[3])
                 : "r"(a[0]), "r"(a[1]), "r"(a[2]), "r"(a[3]), "r"(b0), "r"(b1));
}

// ---------------------------------------------------------------------------
// Shared GEMM geometry: BM=BN=128, 256 thr, 8 warps of 64x32, 4 stages,
// element = b16 unit (bf16, or fp8-pair), BK=32 units, PADK=40 units.
// ---------------------------------------------------------------------------
#define STAGES 4
#define BK 32
#define PADK 40
#define STAGE_BYTES (2 * 128 * PADK * 2)     // 20480
#define KITERS (DM / BK)                     // 64 (both GEMMs: 2048 b16 units)

// ---------------------------------------------------------------------------
// bf16 main GEMM (NT): C = A(4096x2048) * B(2048x2048)^T + corr + bias
// ---------------------------------------------------------------------------
__global__ __launch_bounds__(256) void gemm_bf16(
    const __nv_bfloat16* __restrict__ A, const __nv_bfloat16* __restrict__ B,
    const float* __restrict__ bias, const float* __restrict__ corr,
    float* __restrict__ C)
{
    extern __shared__ __nv_bfloat16 sh[];
    const int bm = blockIdx.y * 128, bn = blockIdx.x * 128;
    const int tid = threadIdx.x, lane = tid & 31, warp = tid >> 5;
    const int wm = (warp >> 2) * 64, wn = (warp & 3) * 32;

    uint32_t sbase = (uint32_t)__cvta_generic_to_shared(sh);

    const int r0 = tid >> 2, seg = (tid & 3) * 8;
    uint32_t dA0 = sbase + (r0 * PADK + seg) * 2;
    uint32_t dA1 = sbase + ((r0 + 64) * PADK + seg) * 2;
    uint32_t dB0 = sbase + (128 * PADK + r0 * PADK + seg) * 2;
    uint32_t dB1 = dB0 + 64 * PADK * 2;
    const __nv_bfloat16* gA0 = A + (size_t)(bm + r0) * DM + seg;
    const __nv_bfloat16* gA1 = A + (size_t)(bm + r0 + 64) * DM + seg;
    const __nv_bfloat16* gB0 = B + (size_t)(bn + r0) * DM + seg;
    const __nv_bfloat16* gB1 = B + (size_t)(bn + r0 + 64) * DM + seg;

    uint32_t aoff[4], boff[2];
    #pragma unroll
    for (int mi = 0; mi < 4; mi++)
        aoff[mi] = ((wm + mi * 16 + (lane & 15)) * PADK + (lane >> 4) * 8) * 2;
    #pragma unroll
    for (int nh = 0; nh < 2; nh++)
        boff[nh] = (128 * PADK + (wn + nh * 16 + (lane >> 4) * 8 + (lane & 7)) * PADK
                    + ((lane >> 3) & 1) * 8) * 2;

    float acc[4][4][4] = {};

    auto load_stage = [&](int s) {
        uint32_t so = (uint32_t)(s & (STAGES - 1)) * STAGE_BYTES;
        int k0 = s * BK;
        cp16(dA0 + so, gA0 + k0);
        cp16(dA1 + so, gA1 + k0);
        cp16(dB0 + so, gB0 + k0);
        cp16(dB1 + so, gB1 + k0);
    };

    load_stage(0); cp_commit();
    load_stage(1); cp_commit();
    load_stage(2); cp_commit();

    for (int it = 0; it < KITERS; it++) {
        cp_wait<2>();
        __syncthreads();
        uint32_t sb = sbase + (uint32_t)(it & (STAGES - 1)) * STAGE_BYTES;

        if (it + 3 < KITERS) load_stage(it + 3);
        cp_commit();

        #pragma unroll
        for (int ks = 0; ks < 2; ks++) {
            uint32_t ko = sb + ks * 32;
            uint32_t a[4][4], b[2][4];
            #pragma unroll
            for (int mi = 0; mi < 4; mi++) ldsm_x4(a[mi], ko + aoff[mi]);
            #pragma unroll
            for (int nh = 0; nh < 2; nh++) ldsm_x4(b[nh], ko + boff[nh]);
            #pragma unroll
            for (int mi = 0; mi < 4; mi++)
                #pragma unroll
                for (int ni = 0; ni < 4; ni++)
                    mma_bf16(acc[mi][ni], a[mi], b[ni >> 1][(ni & 1) * 2],
                             b[ni >> 1][(ni & 1) * 2 + 1]);
        }
    }

    const int er = lane >> 2, ec = (lane & 3) * 2;
    #pragma unroll
    for (int mi = 0; mi < 4; mi++) {
        int row = bm + wm + mi * 16 + er;
        #pragma unroll
        for (int ni = 0; ni < 4; ni++) {
            int col = bn + wn + ni * 8 + ec;
            float b0 = 0.f, b1 = 0.f;
            if (bias) { b0 = bias[col]; b1 = bias[col + 1]; }
            float2 c0 = *(const float2*)&corr[(size_t)row * DM + col];
            float2 c1 = *(const float2*)&corr[(size_t)(row + 8) * DM + col];
            float2 v;
            v.x = acc[mi][ni][0] + b0 + c0.x; v.y = acc[mi][ni][1] + b1 + c0.y;
            *(float2*)&C[(size_t)row * DM + col] = v;
            v.x = acc[mi][ni][2] + b0 + c1.x; v.y = acc[mi][ni][3] + b1 + c1.y;
            *(float2*)&C[(size_t)(row + 8) * DM + col] = v;
        }
    }
}

// ---------------------------------------------------------------------------
// fp8 correction GEMM (NT): corr = (A'(4096x4096e4m3) * B'(2048x4096e4m3)^T)/256
// Identical pipeline; element = b16 unit (= pair of fp8), KU=2048 units.
// ---------------------------------------------------------------------------
__global__ __launch_bounds__(256) void gemm_fp8(
    const uint16_t* __restrict__ A, const uint16_t* __restrict__ B,
    float* __restrict__ C)
{
    extern __shared__ __nv_bfloat16 sh[];
    const int bm = blockIdx.y * 128, bn = blockIdx.x * 128;
    const int tid = threadIdx.x, lane = tid & 31, warp = tid >> 5;
    const int wm = (warp >> 2) * 64, wn = (warp & 3) * 32;

    uint32_t sbase = (uint32_t)__cvta_generic_to_shared(sh);

    const int r0 = tid >> 2, seg = (tid & 3) * 8;
    uint32_t dA0 = sbase + (r0 * PADK + seg) * 2;
    uint32_t dA1 = sbase + ((r0 + 64) * PADK + seg) * 2;
    uint32_t dB0 = sbase + (128 * PADK + r0 * PADK + seg) * 2;
    uint32_t dB1 = dB0 + 64 * PADK * 2;
    const uint16_t* gA0 = A + (size_t)(bm + r0) * KU + seg;
    const uint16_t* gA1 = A + (size_t)(bm + r0 + 64) * KU + seg;
    const uint16_t* gB0 = B + (size_t)(bn + r0) * KU + seg;
    const uint16_t* gB1 = B + (size_t)(bn + r0 + 64) * KU + seg;

    uint32_t aoff[4], boff[2];
    #pragma unroll
    for (int mi = 0; mi < 4; mi++)
        aoff[mi] = ((wm + mi * 16 + (lane & 15)) * PADK + (lane >> 4) * 8) * 2;
    #pragma unroll
    for (int nh = 0; nh < 2; nh++)
        boff[nh] = (128 * PADK + (wn + nh * 16 + (lane >> 4) * 8 + (lane & 7)) * PADK
                    + ((lane >> 3) & 1) * 8) * 2;

    float acc[4][4][4] = {};

    auto load_stage = [&](int s) {
        uint32_t so = (uint32_t)(s & (STAGES - 1)) * STAGE_BYTES;
        int k0 = s * BK;
        cp16(dA0 + so, gA0 + k0);
        cp16(dA1 + so, gA1 + k0);
        cp16(dB0 + so, gB0 + k0);
        cp16(dB1 + so, gB1 + k0);
    };

    load_stage(0); cp_commit();
    load_stage(1); cp_commit();
    load_stage(2); cp_commit();

    for (int it = 0; it < KITERS; it++) {
        cp_wait<2>();
        __syncthreads();
        uint32_t sb = sbase + (uint32_t)(it & (STAGES - 1)) * STAGE_BYTES;

        if (it + 3 < KITERS) load_stage(it + 3);
        cp_commit();

        #pragma unroll
        for (int ks = 0; ks < 2; ks++) {
            uint32_t ko = sb + ks * 32;
            uint32_t a[4][4], b[2][4];
            #pragma unroll
            for (int mi = 0; mi < 4; mi++) ldsm_x4(a[mi], ko + aoff[mi]);
            #pragma unroll
            for (int nh = 0; nh < 2; nh++) ldsm_x4(b[nh], ko + boff[nh]);
            #pragma unroll
            for (int mi = 0; mi < 4; mi++)
                #pragma unroll
                for (int ni = 0; ni < 4; ni++)
                    mma_e4m3(acc[mi][ni], a[mi], b[ni >> 1][(ni & 1) * 2],
                             b[ni >> 1][(ni & 1) * 2 + 1]);
        }
    }

    const float sc = 1.f / 256.f;
    const int er = lane >> 2, ec = (lane & 3) * 2;
    #pragma unroll
    for (int mi = 0; mi < 4; mi++) {
        int row = bm + wm + mi * 16 + er;
        #pragma unroll
        for (int ni = 0; ni < 4; ni++) {
            int col = bn + wn + ni * 8 + ec;
            float2 v;
            v.x = acc[mi][ni][0] * sc; v.y = acc[mi][ni][1] * sc;
            *(float2*)&C[(size_t)row * DM + col] = v;
            v.x = acc[mi][ni][2] * sc; v.y = acc[mi][ni][3] * sc;
            *(float2*)&C[(size_t)(row + 8) * DM + col] = v;
        }
    }
}

// ---------------------------------------------------------------------------
// emit helpers: bf16 hi + fp8 pair (exact 2^8 internal scaling)
// ---------------------------------------------------------------------------
__device__ __forceinline__ uint8_t e4m3(float v) {
    return (uint8_t)__nv_cvt_float_to_fp8(v, __NV_SATFINITE, __NV_E4M3);
}
// acts: A' = [e4m3(a) | e4m3(al*256)]
__device__ __forceinline__ void emit_act(float v, int m, int n,
                                         __nv_bfloat16* ah, uint8_t* aq) {
    __nv_bfloat16 h = __float2bfloat16(v);
    float al = v - __bfloat162float(h);
    ah[(size_t)m * DM + n] = h;
    aq[(size_t)m * KQ + n]      = e4m3(v);
    aq[(size_t)m * KQ + DM + n] = e4m3(al * 256.f);
}
// weights: B' = [e4m3(wl*256) | e4m3(w)]
__device__ __forceinline__ void emit_wt(float v, int n, int k,
                                        __nv_bfloat16* wh, uint8_t* wq) {
    __nv_bfloat16 h = __float2bfloat16(v);
    float wl = v - __bfloat162float(h);
    wh[(size_t)n * DM + k] = h;
    wq[(size_t)n * KQ + k]      = e4m3(wl * 256.f);
    wq[(size_t)n * KQ + DM + k] = e4m3(v);
}

// ---------------------------------------------------------------------------
// BatchNorm (two-phase stats)
// ---------------------------------------------------------------------------
__global__ void bnp1(const float* __restrict__ x)
{
    const int col = blockIdx.x * 32 + (threadIdx.x & 31);
    const int r0  = threadIdx.x >> 5;
    const int t0  = blockIdx.y * 512;
    float s = 0.f, ss = 0.f;
    for (int t = t0 + r0; t < t0 + 512; t += 8) {
        float v = x[(size_t)t * DM + col];
        s += v; ss += v * v;
    }
    __shared__ float sh_s[8][32], sh_ss[8][32];
    sh_s[r0][threadIdx.x & 31]  = s;
    sh_ss[r0][threadIdx.x & 31] = ss;
    __syncthreads();
    if (r0 == 0) {
        for (int r = 1; r < 8; r++) {
            s  += sh_s[r][threadIdx.x & 31];
            ss += sh_ss[r][threadIdx.x & 31];
        }
        g_bnp[blockIdx.y][0][col] = s;
        g_bnp[blockIdx.y][1][col] = ss;
    }
}

__global__ void bnp2()
{
    int col = blockIdx.x * blockDim.x + threadIdx.x;
    float s = 0.f, ss = 0.f;
    #pragma unroll
    for (int r = 0; r < 8; r++) { s += g_bnp[r][0][col]; ss += g_bnp[r][1][col]; }
    float mu = s / (float)T_SEQ;
    g_mean[col] = mu;
    g_var[col]  = ss / (float)T_SEQ - mu * mu;
}

__global__ void bn_fuse(const float* __restrict__ x, float* __restrict__ xn,
                        __nv_bfloat16* __restrict__ ah, uint8_t* __restrict__ aq,
                        const float* __restrict__ w, const float* __restrict__ b)
{
    int idx = blockIdx.x * blockDim.x + threadIdx.x;
    int n = idx & (DM - 1);
    int m = idx >> 11;
    float inv = rsqrtf(g_var[n] + BN_EPS);
    float v = (x[idx] - g_mean[n]) * inv * w[n] + b[n];
    xn[idx] = v;
    emit_act(v, m, n, ah, aq);
}

// ---------------------------------------------------------------------------
// Weight packing
// ---------------------------------------------------------------------------
__global__ void pack_w_plain(const float* __restrict__ W,
                             __nv_bfloat16* __restrict__ wh, uint8_t* __restrict__ wq)
{
    int idx = blockIdx.x * blockDim.x + threadIdx.x;
    int n = idx >> 11, k = idx & (DM - 1);
    emit_wt(W[idx], n, k, wh, wq);
}

__global__ void pack_Bn(const float* __restrict__ B_re, const float* __restrict__ B_im,
                        const float* __restrict__ gamma_log,
                        __nv_bfloat16* __restrict__ wh, uint8_t* __restrict__ wq)
{
    int idx = blockIdx.x * blockDim.x + threadIdx.x;
    int n = idx >> 11, k = idx & (DM - 1);
    int jj = n & (DH - 1);
    float g = expf(gamma_log[jj]);
    float v = ((n < DH) ? B_re[(size_t)jj * DM + k] : B_im[(size_t)jj * DM + k]) * g;
    emit_wt(v, n, k, wh, wq);
}

__global__ void pack_Cc(const float* __restrict__ C_re, const float* __restrict__ C_im,
                        __nv_bfloat16* __restrict__ wh, uint8_t* __restrict__ wq)
{
    int idx = blockIdx.x * blockDim.x + threadIdx.x;
    int n = idx >> 11, k = idx & (DM - 1);
    float v = (k < DH) ? C_re[(size_t)n * DH + k] : -C_im[(size_t)n * DH + (k - DH)];
    emit_wt(v, n, k, wh, wq);
}

__global__ void pack_act_plain(const float* __restrict__ X,
                               __nv_bfloat16* __restrict__ ah, uint8_t* __restrict__ aq)
{
    int idx = blockIdx.x * blockDim.x + threadIdx.x;
    int n = idx & (DM - 1);
    int m = idx >> 11;
    emit_act(X[idx], m, n, ah, aq);
}

// ---------------------------------------------------------------------------
// LRU scan — chunk-parallel (3 passes)
// ---------------------------------------------------------------------------
__device__ __forceinline__ void lam_of(int j, const float* nu_log, const float* th_log,
                                       float& lr, float& li)
{
    float mag = expf(-expf(nu_log[j]));
    float ph  = expf(th_log[j]);
    lr = mag * cosf(ph);
    li = mag * sinf(ph);
}

__global__ void scan_p1(const float* __restrict__ Bu,
                        const float* __restrict__ nu_log, const float* __restrict__ th_log)
{
    int idx = blockIdx.x * blockDim.x + threadIdx.x;
    int j = idx & (DH - 1), c = idx >> 10;
    float lr, li; lam_of(j, nu_log, th_log, lr, li);
    float hr = 0.f, hi = 0.f;
    int t0 = c * SCHL;
    for (int t = t0; t < t0 + SCHL; t++) {
        float br = Bu[(size_t)t * DM + j];
        float bi = Bu[(size_t)t * DM + DH + j];
        float nhr = lr * hr - li * hi + br;
        float nhi = lr * hi + li * hr + bi;
        hr = nhr; hi = nhi;
    }
    g_carr[c * DH + j] = hr;
    g_cari[c * DH + j] = hi;
}

__global__ void scan_fix(const float* __restrict__ nu_log, const float* __restrict__ th_log)
{
    int j = blockIdx.x * blockDim.x + threadIdx.x;
    float lr, li; lam_of(j, nu_log, th_log, lr, li);
    float ar = lr, ai = li;
    #pragma unroll
    for (int s = 0; s < 8; s++) {       // lam^256
        float nr = ar * ar - ai * ai;
        float ni = 2.f * ar * ai;
        ar = nr; ai = ni;
    }
    float cr = 0.f, ci = 0.f;
    for (int c = 0; c < SCH; c++) {
        g_cinr[c * DH + j] = cr;
        g_cini[c * DH + j] = ci;
        float nr = ar * cr - ai * ci + g_carr[c * DH + j];
        float ni = ar * ci + ai * cr + g_cari[c * DH + j];
        cr = nr; ci = ni;
    }
}

__global__ void scan_p2(const float* __restrict__ Bu,
                        __nv_bfloat16* __restrict__ ah, uint8_t* __restrict__ aq,
                        const float* __restrict__ nu_log, const float* __restrict__ th_log)
{
    int idx = blockIdx.x * blockDim.x + threadIdx.x;
    int j = idx & (DH - 1), c = idx >> 10;
    float lr, li; lam_of(j, nu_log, th_log, lr, li);
    float hr = g_cinr[c * DH + j], hi = g_cini[c * DH + j];
    int t0 = c * SCHL;
    for (int t = t0; t < t0 + SCHL; t++) {
        float br = Bu[(size_t)t * DM + j];
        float bi = Bu[(size_t)t * DM + DH + j];
        float nhr = lr * hr - li * hi + br;
        float nhi = lr * hi + li * hr + bi;
        hr = nhr; hi = nhi;
        emit_act(hr, t, j, ah, aq);
        emit_act(hi, t, DH + j, ah, aq);
    }
}

// ---------------------------------------------------------------------------
// Epilogues
// ---------------------------------------------------------------------------
__global__ void posty_fuse(const float* __restrict__ y, const float* __restrict__ xn,
                           const float* __restrict__ Dv,
                           __nv_bfloat16* __restrict__ ah, uint8_t* __restrict__ aq)
{
    int idx = blockIdx.x * blockDim.x + threadIdx.x;
    int n = idx & (DM - 1);
    int m = idx >> 11;
    float v = y[idx] + xn[idx] * Dv[n];
    float g = 0.5f * v * (1.f + erff(v * 0.70710678118654752f));
    emit_act(g, m, n, ah, aq);
}

__global__ void glu_combine(const float* __restrict__ x, const float* __restrict__ u,
                            const float* __restrict__ v, float* __restrict__ out)
{
    int idx = blockIdx.x * blockDim.x + threadIdx.x;
    float vv = v[idx];
    float s = 1.f / (1.f + expf(-vv));
    out[idx] = x[idx] + u[idx] * s;
}

// ---------------------------------------------------------------------------
// Launch
// ---------------------------------------------------------------------------
extern "C" void kernel_launch(void* const* d_in, const int* in_sizes, int n_in,
                              void* d_out, int out_size)
{
    const float* x_in      = (const float*)d_in[0];
    const float* enc_w     = (const float*)d_in[1];
    const float* enc_b     = (const float*)d_in[2];
    const float* nu_log    = (const float*)d_in[3];
    const float* theta_log = (const float*)d_in[4];
    const float* gamma_log = (const float*)d_in[5];
    const float* B_re      = (const float*)d_in[6];
    const float* B_im      = (const float*)d_in[7];
    const float* C_re      = (const float*)d_in[8];
    const float* C_im      = (const float*)d_in[9];
    const float* Dv        = (const float*)d_in[10];
    const float* norm_w    = (const float*)d_in[11];
    const float* norm_b    = (const float*)d_in[12];
    const float* out1_w    = (const float*)d_in[13];
    const float* out1_b    = (const float*)d_in[14];
    const float* out2_w    = (const float*)d_in[15];
    const float* out2_b    = (const float*)d_in[16];
    float* out = (float*)d_out;
    (void)in_sizes; (void)n_in; (void)out_size;

    float *px, *pxn, *pt1, *pu, *pv, *pcorr;
    __nv_bfloat16 *pah, *pwh;
    uint8_t *paq, *pwq;
    cudaGetSymbolAddress((void**)&px,    g_x);
    cudaGetSymbolAddress((void**)&pxn,   g_xn);
    cudaGetSymbolAddress((void**)&pt1,   g_t1);
    cudaGetSymbolAddress((void**)&pu,    g_u);
    cudaGetSymbolAddress((void**)&pv,    g_v);
    cudaGetSymbolAddress((void**)&pcorr, g_corr);
    cudaGetSymbolAddress((void**)&pah,   g_ah);
    cudaGetSymbolAddress((void**)&paq,   g_aq);
    cudaGetSymbolAddress((void**)&pwh,   g_wh);
    cudaGetSymbolAddress((void**)&pwq,   g_wq);

    const int SMEM = STAGES * STAGE_BYTES;   // 81920
    cudaFuncSetAttribute(gemm_bf16, cudaFuncAttributeMaxDynamicSharedMemorySize, SMEM);
    cudaFuncSetAttribute(gemm_fp8,  cudaFuncAttributeMaxDynamicSharedMemorySize, SMEM);

    dim3 ggrid(DM / 128, T_SEQ / 128);   // (16, 32)
    const int EW = (T_SEQ * DM) / 256;
    const int PW = (DM * DM) / 256;
    dim3 bgrid(DM / 32, 8);
    const uint16_t* paq16 = (const uint16_t*)paq;
    const uint16_t* pwq16 = (const uint16_t*)pwq;

    // Encoder
    pack_act_plain<<<EW, 256>>>(x_in, pah, paq);
    pack_w_plain<<<PW, 256>>>(enc_w, pwh, pwq);
    gemm_fp8<<<ggrid, 256, SMEM>>>(paq16, pwq16, pcorr);
    gemm_bf16<<<ggrid, 256, SMEM>>>(pah, pwh, enc_b, pcorr, px);

    for (int l = 0; l < L_LAYERS; l++) {
        const float* nw  = norm_w + l * DM;
        const float* nb  = norm_b + l * DM;
        const float* nu  = nu_log + l * DH;
        const float* th  = theta_log + l * DH;
        const float* gl  = gamma_log + l * DH;
        const float* bre = B_re + (size_t)l * DH * DM;
        const float* bim = B_im + (size_t)l * DH * DM;
        const float* cre = C_re + (size_t)l * DM * DH;
        const float* cim = C_im + (size_t)l * DM * DH;
        const float* dv  = Dv + l * DM;
        const float* w1  = out1_w + (size_t)l * DM * DM;
        const float* b1  = out1_b + l * DM;
        const float* w2  = out2_w + (size_t)l * DM * DM;
        const float* b2  = out2_b + l * DM;

        bnp1<<<bgrid, 256>>>(px);
        bnp2<<<DM / 256, 256>>>();
        bn_fuse<<<EW, 256>>>(px, pxn, pah, paq, nw, nb);

        pack_Bn<<<PW, 256>>>(bre, bim, gl, pwh, pwq);
        gemm_fp8<<<ggrid, 256, SMEM>>>(paq16, pwq16, pcorr);
        gemm_bf16<<<ggrid, 256, SMEM>>>(pah, pwh, nullptr, pcorr, pt1);   // Bu

        scan_p1<<<(DH * SCH) / 256, 256>>>(pt1, nu, th);
        scan_fix<<<DH / 256, 256>>>(nu, th);
        scan_p2<<<(DH * SCH) / 256, 256>>>(pt1, pah, paq, nu, th);

        pack_Cc<<<PW, 256>>>(cre, cim, pwh, pwq);
        gemm_fp8<<<ggrid, 256, SMEM>>>(paq16, pwq16, pcorr);
        gemm_bf16<<<ggrid, 256, SMEM>>>(pah, pwh, nullptr, pcorr, pt1);   // y raw

        posty_fuse<<<EW, 256>>>(pt1, pxn, dv, pah, paq);

        pack_w_plain<<<PW, 256>>>(w1, pwh, pwq);
        gemm_fp8<<<ggrid, 256, SMEM>>>(paq16, pwq16, pcorr);
        gemm_bf16<<<ggrid, 256, SMEM>>>(pah, pwh, b1, pcorr, pu);

        pack_w_plain<<<PW, 256>>>(w2, pwh, pwq);
        gemm_fp8<<<ggrid, 256, SMEM>>>(paq16, pwq16, pcorr);
        gemm_bf16<<<ggrid, 256, SMEM>>>(pah, pwh, b2, pcorr, pv);

        float* dst = (l == L_LAYERS - 1) ? out : px;
        glu_combine<<<EW, 256>>>(px, pu, pv, dst);
    }
}